// round 6
// baseline (speedup 1.0000x reference)
#include <cuda_runtime.h>
#include <cuda_bf16.h>
#include <cstdint>
#include <math.h>

// ---------------- problem constants ----------------
#define BATCH     2
#define TQ        197
#define DIMM      256
#define HEADS     4
#define DH        64
#define FIVE      1280
#define MLPD      1024
#define NCLS      1000
#define PATCH_DIM 768
#define NPATCH    196
#define MROWS     (BATCH*TQ)     // 394

// ---------------- tritt v2 constants ----------------
#define TT_THREADS 256
#define MPAD       256
#define BROWS      208
#define QB         4
#define NQCHUNK    50            // ceil(197/4)

// dynamic smem byte offsets (A/B must be 1024-aligned for swizzle)
#define SMB_RED    0                        // 32 floats
#define SMB_CVEC   128                      // 64 floats
#define SMB_ROWM   384                      // 208 floats (832 B)
#define SMB_COLM   1216                     // 208 floats
#define SMB_SCR    2048                     // 256 floats (1024 B)
#define SMB_A      3072                     // 256 x 128B bf16 swizzled
#define SMB_B      (SMB_A + MPAD*128)       // 35840: 208 x 128B
#define SMB_D      (SMB_B + BROWS*128)      // 62464: 197x64 bf16
#define SMB_E      (SMB_D + TQ*DH*2)        // 87680
#define SMB_TOTAL  (SMB_E + TQ*DH*2)        // 112896 bytes

__device__ __forceinline__ uint32_t swz(uint32_t off) {
    return off ^ ((off >> 3) & 0x70);
}

// ---------------- device scratch ----------------
__device__ float g_pn[BATCH*NPATCH*PATCH_DIM];
__device__ float g_t1[BATCH*NPATCH*DIMM];
__device__ float g_x[MROWS*DIMM];
__device__ float g_xn[MROWS*DIMM];
__device__ float g_ab[MROWS*FIVE];
__device__ float g_z[MROWS*DIMM];
__device__ float g_h[MROWS*MLPD];
__device__ float g_part[4*MROWS*DIMM];   // split-K partials (max 4 slabs)

// ---------------- PTX helpers ----------------
__device__ __forceinline__ uint32_t smem_u32(const void* p) {
    uint32_t a;
    asm("{ .reg .u64 t; cvta.to.shared.u64 t, %1; cvt.u32.u64 %0, t; }" : "=r"(a) : "l"(p));
    return a;
}
__device__ __forceinline__ void ldm_x4(uint32_t addr, uint32_t* r) {
    asm volatile("ldmatrix.sync.aligned.m8n8.x4.shared.b16 {%0,%1,%2,%3}, [%4];"
                 : "=r"(r[0]), "=r"(r[1]), "=r"(r[2]), "=r"(r[3]) : "r"(addr));
}
__device__ __forceinline__ void ldm_x2(uint32_t addr, uint32_t* r) {
    asm volatile("ldmatrix.sync.aligned.m8n8.x2.shared.b16 {%0,%1}, [%2];"
                 : "=r"(r[0]), "=r"(r[1]) : "r"(addr));
}
__device__ __forceinline__ void mma16816(float* c, const uint32_t* a, const uint32_t* b) {
    asm volatile("mma.sync.aligned.m16n8k16.row.col.f32.bf16.bf16.f32 "
                 "{%0,%1,%2,%3}, {%4,%5,%6,%7}, {%8,%9}, {%0,%1,%2,%3};"
                 : "+f"(c[0]), "+f"(c[1]), "+f"(c[2]), "+f"(c[3])
                 : "r"(a[0]), "r"(a[1]), "r"(a[2]), "r"(a[3]), "r"(b[0]), "r"(b[1]));
}
__device__ __forceinline__ uint32_t hmul2u(uint32_t a, uint32_t b) {
    __nv_bfloat162 x = *(__nv_bfloat162*)&a, y = *(__nv_bfloat162*)&b;
    __nv_bfloat162 z = __hmul2(x, y);
    return *(uint32_t*)&z;
}

// ---------------- reductions (blockDim == 256, 8 warps) ----------------
__device__ __forceinline__ float block_reduce_sum(float v, float* red) {
    #pragma unroll
    for (int o = 16; o > 0; o >>= 1) v += __shfl_xor_sync(0xffffffffu, v, o);
    if ((threadIdx.x & 31) == 0) red[threadIdx.x >> 5] = v;
    __syncthreads();
    if (threadIdx.x < 32) {
        float r = (threadIdx.x < 8) ? red[threadIdx.x] : 0.f;
        #pragma unroll
        for (int o = 4; o > 0; o >>= 1) r += __shfl_xor_sync(0xffffffffu, r, o);
        if (threadIdx.x == 0) red[0] = r;
    }
    __syncthreads();
    float out = red[0];
    __syncthreads();
    return out;
}
__device__ __forceinline__ float block_reduce_max(float v, float* red) {
    #pragma unroll
    for (int o = 16; o > 0; o >>= 1) v = fmaxf(v, __shfl_xor_sync(0xffffffffu, v, o));
    if ((threadIdx.x & 31) == 0) red[threadIdx.x >> 5] = v;
    __syncthreads();
    if (threadIdx.x < 32) {
        float r = (threadIdx.x < 8) ? red[threadIdx.x] : -1e30f;
        #pragma unroll
        for (int o = 4; o > 0; o >>= 1) r = fmaxf(r, __shfl_xor_sync(0xffffffffu, r, o));
        if (threadIdx.x == 0) red[0] = r;
    }
    __syncthreads();
    float out = red[0];
    __syncthreads();
    return out;
}

// ---------------- patch gather ----------------
__global__ void gather_kernel(const float* __restrict__ img) {
    int row = blockIdx.x;
    int b = row / NPATCH, pidx = row % NPATCH;
    int gh = pidx / 14, gw = pidx % 14;
    for (int j = threadIdx.x; j < PATCH_DIM; j += 256) {
        int p1 = j / 48, rem = j % 48, p2 = rem / 3, c = rem % 3;
        g_pn[(size_t)row*PATCH_DIM + j] =
            img[(((size_t)b*3 + c)*224 + gh*16 + p1)*224 + gw*16 + p2];
    }
}

// ---------------- generic LayerNorm ----------------
__global__ void ln_kernel(const float* __restrict__ X, const float* __restrict__ g,
                          const float* __restrict__ bv, float* __restrict__ Y, int width) {
    __shared__ float red[32];
    int row = blockIdx.x;
    const float* x = X + (size_t)row*width;
    float s = 0.f;
    for (int j = threadIdx.x; j < width; j += 256) s += x[j];
    float mean = block_reduce_sum(s, red) / (float)width;
    float vs = 0.f;
    for (int j = threadIdx.x; j < width; j += 256) { float d = x[j]-mean; vs += d*d; }
    float var = block_reduce_sum(vs, red) / (float)width;
    float inv = rsqrtf(var + 1e-5f);
    for (int j = threadIdx.x; j < width; j += 256)
        Y[(size_t)row*width + j] = (x[j]-mean)*inv*g[j] + bv[j];
}

// ---------------- assemble tokens: LN2 + cls + pos ----------------
__global__ void assemble_kernel(const float* __restrict__ t1, const float* __restrict__ g,
                                const float* __restrict__ bv, const float* __restrict__ cls,
                                const float* __restrict__ pos, float* __restrict__ X) {
    __shared__ float red[32];
    int row = blockIdx.x;
    int b = row / TQ, t = row % TQ;
    if (t == 0) {
        for (int j = threadIdx.x; j < DIMM; j += 256)
            X[(size_t)row*DIMM + j] = cls[j] + pos[j];
    } else {
        const float* x = t1 + (size_t)(b*NPATCH + t - 1)*DIMM;
        float s = 0.f;
        for (int j = threadIdx.x; j < DIMM; j += 256) s += x[j];
        float mean = block_reduce_sum(s, red) * (1.f/DIMM);
        float vs = 0.f;
        for (int j = threadIdx.x; j < DIMM; j += 256) { float d = x[j]-mean; vs += d*d; }
        float var = block_reduce_sum(vs, red) * (1.f/DIMM);
        float inv = rsqrtf(var + 1e-5f);
        for (int j = threadIdx.x; j < DIMM; j += 256)
            X[(size_t)row*DIMM + j] = (x[j]-mean)*inv*g[j] + bv[j] + pos[t*DIMM + j];
    }
}

// ---------------- generic fp32 GEMM (direct form) ----------------
__device__ __forceinline__ float gelu_exact(float v) {
    return 0.5f * v * (1.f + erff(v * 0.70710678118654752f));
}

template<int ACT>
__global__ void gemm_kernel(const float* __restrict__ A, const float* __restrict__ W,
                            const float* __restrict__ bias, const float* __restrict__ R,
                            float* __restrict__ C, int M, int K, int N) {
    __shared__ float As[16][68];
    __shared__ float Ws[16][68];
    int tid = threadIdx.x;
    int tx = tid & 15, ty = tid >> 4;
    int m0 = blockIdx.y * 64, n0 = blockIdx.x * 64;
    float acc[4][4];
    #pragma unroll
    for (int i = 0; i < 4; i++)
        #pragma unroll
        for (int j = 0; j < 4; j++) acc[i][j] = 0.f;

    int am = tid >> 2, ak = (tid & 3) << 2;
    int wk = tid >> 4, wn = (tid & 15) << 2;

    for (int k0 = 0; k0 < K; k0 += 16) {
        float4 av = make_float4(0.f, 0.f, 0.f, 0.f);
        if (m0 + am < M)
            av = *(const float4*)&A[(size_t)(m0 + am)*K + k0 + ak];
        As[ak + 0][am] = av.x; As[ak + 1][am] = av.y;
        As[ak + 2][am] = av.z; As[ak + 3][am] = av.w;
        #pragma unroll
        for (int e = 0; e < 4; e++) {
            int n = n0 + wn + e;
            Ws[wk][wn + e] = (n < N) ? W[(size_t)(k0 + wk)*N + n] : 0.f;
        }
        __syncthreads();
        #pragma unroll
        for (int k = 0; k < 16; k++) {
            float a0 = As[k][ty*4+0], a1 = As[k][ty*4+1];
            float a2 = As[k][ty*4+2], a3 = As[k][ty*4+3];
            float w0 = Ws[k][tx*4+0], w1 = Ws[k][tx*4+1];
            float w2 = Ws[k][tx*4+2], w3 = Ws[k][tx*4+3];
            acc[0][0] += a0*w0; acc[0][1] += a0*w1; acc[0][2] += a0*w2; acc[0][3] += a0*w3;
            acc[1][0] += a1*w0; acc[1][1] += a1*w1; acc[1][2] += a1*w2; acc[1][3] += a1*w3;
            acc[2][0] += a2*w0; acc[2][1] += a2*w1; acc[2][2] += a2*w2; acc[2][3] += a2*w3;
            acc[3][0] += a3*w0; acc[3][1] += a3*w1; acc[3][2] += a3*w2; acc[3][3] += a3*w3;
        }
        __syncthreads();
    }
    #pragma unroll
    for (int i = 0; i < 4; i++) {
        int m = m0 + ty*4 + i;
        if (m >= M) continue;
        #pragma unroll
        for (int j = 0; j < 4; j++) {
            int n = n0 + tx*4 + j;
            if (n >= N) continue;
            float v = acc[i][j] + bias[n];
            if (ACT == 1) v = gelu_exact(v);
            if (R != nullptr) v += R[(size_t)m*N + n];
            C[(size_t)m*N + n] = v;
        }
    }
}

// ---------------- split-K GEMM: partial slabs, no bias/act ----------------
__global__ void gemm_part_kernel(const float* __restrict__ A, const float* __restrict__ W,
                                 float* __restrict__ P, int M, int N, int klen) {
    __shared__ float As[16][68];
    __shared__ float Ws[16][68];
    int tid = threadIdx.x;
    int tx = tid & 15, ty = tid >> 4;
    int m0 = blockIdx.y * 64, n0 = blockIdx.x * 64;
    int kstart = blockIdx.z * klen;
    float* C = P + (size_t)blockIdx.z * M * N;
    float acc[4][4];
    #pragma unroll
    for (int i = 0; i < 4; i++)
        #pragma unroll
        for (int j = 0; j < 4; j++) acc[i][j] = 0.f;

    int am = tid >> 2, ak = (tid & 3) << 2;
    int wk = tid >> 4, wn = (tid & 15) << 2;

    for (int k0 = kstart; k0 < kstart + klen; k0 += 16) {
        float4 av = make_float4(0.f, 0.f, 0.f, 0.f);
        // K here is the full row stride of A; caller guarantees klen*gridDim.z == K
        if (m0 + am < M)
            av = *(const float4*)&A[(size_t)(m0 + am)*(klen*gridDim.z) + k0 + ak];
        As[ak + 0][am] = av.x; As[ak + 1][am] = av.y;
        As[ak + 2][am] = av.z; As[ak + 3][am] = av.w;
        #pragma unroll
        for (int e = 0; e < 4; e++) {
            int n = n0 + wn + e;
            Ws[wk][wn + e] = (n < N) ? W[(size_t)(k0 + wk)*N + n] : 0.f;
        }
        __syncthreads();
        #pragma unroll
        for (int k = 0; k < 16; k++) {
            float a0 = As[k][ty*4+0], a1 = As[k][ty*4+1];
            float a2 = As[k][ty*4+2], a3 = As[k][ty*4+3];
            float w0 = Ws[k][tx*4+0], w1 = Ws[k][tx*4+1];
            float w2 = Ws[k][tx*4+2], w3 = Ws[k][tx*4+3];
            acc[0][0] += a0*w0; acc[0][1] += a0*w1; acc[0][2] += a0*w2; acc[0][3] += a0*w3;
            acc[1][0] += a1*w0; acc[1][1] += a1*w1; acc[1][2] += a1*w2; acc[1][3] += a1*w3;
            acc[2][0] += a2*w0; acc[2][1] += a2*w1; acc[2][2] += a2*w2; acc[2][3] += a2*w3;
            acc[3][0] += a3*w0; acc[3][1] += a3*w1; acc[3][2] += a3*w2; acc[3][3] += a3*w3;
        }
        __syncthreads();
    }
    #pragma unroll
    for (int i = 0; i < 4; i++) {
        int m = m0 + ty*4 + i;
        if (m >= M) continue;
        #pragma unroll
        for (int j = 0; j < 4; j++) {
            int n = n0 + tx*4 + j;
            if (n >= N) continue;
            C[(size_t)m*N + n] = acc[i][j];
        }
    }
}

// combine: C = sum(parts) + bias (+R)
__global__ void combine_kernel(const float* __restrict__ P, int ns,
                               const float* __restrict__ bias, const float* __restrict__ R,
                               float* __restrict__ C, int M, int N) {
    int idx = blockIdx.x * 256 + threadIdx.x;
    if (idx >= M * N) return;
    int n = idx % N;
    float v = bias[n];
    for (int j = 0; j < ns; j++) v += P[(size_t)j*M*N + idx];
    if (R != nullptr) v += R[idx];
    C[idx] = v;
}

// ---------------- tritt v2 tile processor ----------------
template<int NJ>
__device__ __forceinline__ void tt_tile(
    int tt, int tbase, uint32_t su, uint32_t sb, const uint32_t* cs,
    float* redf, float* rowm, float* colm, float& mrun,
    int warp, int lane)
{
    const int tid = threadIdx.x;
    const int g = lane >> 2, t4 = lane & 3;

    float acc[2][NJ][4];
    #pragma unroll
    for (int mc = 0; mc < 2; mc++)
        #pragma unroll
        for (int j = 0; j < NJ; j++)
            #pragma unroll
            for (int r = 0; r < 4; r++) acc[mc][j][r] = 0.f;

    const int arow = (lane & 7) + ((lane >> 3) & 1) * 8;
    const int akb  = (lane >> 4) << 4;
    const int l2   = lane & 15;
    const int brow = l2 & 7;
    const int bkb  = (l2 >> 3) << 4;

    #pragma unroll
    for (int ks = 0; ks < 4; ks++) {
        uint32_t a[2][4];
        #pragma unroll
        for (int mc = 0; mc < 2; mc++) {
            int row = warp*32 + mc*16 + arow;
            ldm_x4(su + swz((uint32_t)(row*128 + ks*32 + akb)), a[mc]);
            // fold c_q (and 1/DH) into A fragments
            a[mc][0] = hmul2u(a[mc][0], cs[ks*2+0]);
            a[mc][1] = hmul2u(a[mc][1], cs[ks*2+0]);
            a[mc][2] = hmul2u(a[mc][2], cs[ks*2+1]);
            a[mc][3] = hmul2u(a[mc][3], cs[ks*2+1]);
        }
        uint32_t b[NJ][2];
        #pragma unroll
        for (int j = 0; j < NJ; j++) {
            int row = tbase + j*8 + brow;
            ldm_x2(sb + swz((uint32_t)(row*128 + ks*32 + bkb)), b[j]);
        }
        #pragma unroll
        for (int mc = 0; mc < 2; mc++)
            #pragma unroll
            for (int j = 0; j < NJ; j++)
                mma16816(acc[mc][j], a[mc], b[j]);
    }

    bool vr[4];
    #pragma unroll
    for (int i = 0; i < 4; i++)
        vr[i] = (warp*32 + (i >> 1)*16 + (i & 1)*8 + g) < TQ;

    float lmax = -1e30f;
    #pragma unroll
    for (int mc = 0; mc < 2; mc++) {
        #pragma unroll
        for (int j = 0; j < NJ; j++) {
            int c0 = tbase + j*8 + 2*t4;
            bool vc0 = c0 < TQ, vc1 = (c0 + 1) < TQ;
            if (vr[mc*2]   && vc0) lmax = fmaxf(lmax, acc[mc][j][0]);
            if (vr[mc*2]   && vc1) lmax = fmaxf(lmax, acc[mc][j][1]);
            if (vr[mc*2+1] && vc0) lmax = fmaxf(lmax, acc[mc][j][2]);
            if (vr[mc*2+1] && vc1) lmax = fmaxf(lmax, acc[mc][j][3]);
        }
    }
    float bmax = block_reduce_max(lmax, redf);
    float mnew = fmaxf(mrun, bmax);
    if (tt > 0 && mnew > mrun && tid < BROWS) {
        float sc = __expf(mrun - mnew);
        rowm[tid] *= sc;
        colm[tid] *= sc;
    }
    mrun = mnew;
    __syncthreads();

    float rsum[4] = {0.f, 0.f, 0.f, 0.f};
    #pragma unroll
    for (int mc = 0; mc < 2; mc++) {
        #pragma unroll
        for (int j = 0; j < NJ; j++) {
            int c0 = tbase + j*8 + 2*t4;
            bool vc0 = c0 < TQ, vc1 = (c0 + 1) < TQ;
            float e0 = (vr[mc*2]   && vc0) ? __expf(acc[mc][j][0] - mrun) : 0.f;
            float e1 = (vr[mc*2]   && vc1) ? __expf(acc[mc][j][1] - mrun) : 0.f;
            float e2 = (vr[mc*2+1] && vc0) ? __expf(acc[mc][j][2] - mrun) : 0.f;
            float e3 = (vr[mc*2+1] && vc1) ? __expf(acc[mc][j][3] - mrun) : 0.f;
            acc[mc][j][0] = e0; acc[mc][j][1] = e1;
            acc[mc][j][2] = e2; acc[mc][j][3] = e3;
            rsum[mc*2]   += e0 + e1;
            rsum[mc*2+1] += e2 + e3;
        }
    }
    #pragma unroll
    for (int i = 0; i < 4; i++) {
        rsum[i] += __shfl_xor_sync(0xffffffffu, rsum[i], 1);
        rsum[i] += __shfl_xor_sync(0xffffffffu, rsum[i], 2);
    }
    if (t4 == 0) {
        #pragma unroll
        for (int i = 0; i < 4; i++) {
            int r = warp*32 + (i >> 1)*16 + (i & 1)*8 + g;
            if (r < TQ) atomicAdd(&rowm[r], rsum[i]);
        }
    }

    #pragma unroll
    for (int j = 0; j < NJ; j++) {
        float cs0 = acc[0][j][0] + acc[0][j][2] + acc[1][j][0] + acc[1][j][2];
        float cs1 = acc[0][j][1] + acc[0][j][3] + acc[1][j][1] + acc[1][j][3];
        #pragma unroll
        for (int o = 4; o <= 16; o <<= 1) {
            cs0 += __shfl_xor_sync(0xffffffffu, cs0, o);
            cs1 += __shfl_xor_sync(0xffffffffu, cs1, o);
        }
        if (g == 0) {
            int c0 = tbase + j*8 + 2*t4;
            if (c0 < TQ && cs0 != 0.f) atomicAdd(&colm[c0], cs0);
            if (c0 + 1 < TQ && cs1 != 0.f) atomicAdd(&colm[c0 + 1], cs1);
        }
    }
    __syncthreads();
}

// ---------------- trittention v2: one CTA per (b, h, q-block of 4) ----------------
__global__ __launch_bounds__(TT_THREADS, 2)
void tritt_mma_kernel(const float* __restrict__ abcde, float* __restrict__ Z) {
    extern __shared__ char smc[];
    float* redf = (float*)(smc + SMB_RED);
    float* cvec = (float*)(smc + SMB_CVEC);
    float* rowm = (float*)(smc + SMB_ROWM);
    float* colm = (float*)(smc + SMB_COLM);
    float* scr  = (float*)(smc + SMB_SCR);
    __nv_bfloat16* smD = (__nv_bfloat16*)(smc + SMB_D);
    __nv_bfloat16* smE = (__nv_bfloat16*)(smc + SMB_E);
    uint32_t su = smem_u32(smc + SMB_A);
    uint32_t sb = smem_u32(smc + SMB_B);

    const int tid = threadIdx.x;
    const int warp = tid >> 5, lane = tid & 31;
    const int t4 = lane & 3;

    int pair = blockIdx.x / NQCHUNK;
    int qc = blockIdx.x % NQCHUNK;
    int b = pair >> 2, h = pair & 3;
    const float* base = abcde + (size_t)b * TQ * FIVE;
    const int hoff = h * DH;
    int q0 = qc * QB;
    int nq = (TQ - q0 < QB) ? (TQ - q0) : QB;

    // ---- per-CTA setup: A raw, B, D, E ----
    for (int idx = tid; idx < MPAD*32; idx += TT_THREADS) {
        int s = idx >> 5, dp = (idx & 31) << 1;
        uint32_t val = 0u;
        if (s < TQ) {
            float2 av = *(const float2*)&base[(size_t)s*FIVE + hoff + dp];
            __nv_bfloat162 pp = __floats2bfloat162_rn(av.x, av.y);
            val = *(uint32_t*)&pp;
        }
        *(uint32_t*)(smc + SMB_A + swz((uint32_t)(s*128 + dp*2))) = val;
    }
    for (int idx = tid; idx < BROWS*32; idx += TT_THREADS) {
        int t = idx >> 5, dp = (idx & 31) << 1;
        uint32_t val = 0u;
        if (t < TQ) {
            float2 bv = *(const float2*)&base[(size_t)t*FIVE + DIMM + hoff + dp];
            __nv_bfloat162 pp = __floats2bfloat162_rn(bv.x, bv.y);
            val = *(uint32_t*)&pp;
        }
        *(uint32_t*)(smc + SMB_B + swz((uint32_t)(t*128 + dp*2))) = val;
    }
    for (int idx = tid; idx < TQ*32; idx += TT_THREADS) {
        int s = idx >> 5, dpp = idx & 31;
        float2 dv = *(const float2*)&base[(size_t)s*FIVE + 3*DIMM + hoff + dpp*2];
        float2 ev = *(const float2*)&base[(size_t)s*FIVE + 4*DIMM + hoff + dpp*2];
        __nv_bfloat162 dd = __floats2bfloat162_rn(dv.x, dv.y);
        __nv_bfloat162 ee = __floats2bfloat162_rn(ev.x, ev.y);
        ((uint32_t*)smD)[s*32 + dpp] = *(uint32_t*)&dd;
        ((uint32_t*)smE)[s*32 + dpp] = *(uint32_t*)&ee;
    }
    __syncthreads();

    // ---- per-q loop ----
    for (int iq = 0; iq < nq; iq++) {
        int q = q0 + iq;
        if (tid < DH)
            cvec[tid] = base[(size_t)q*FIVE + 2*DIMM + hoff + tid] * (1.0f/DH);
        if (tid < BROWS) { rowm[tid] = 0.f; colm[tid] = 0.f; }
        __syncthreads();

        // per-thread c-scale pairs for the 4 k-slabs
        uint32_t cs[8];
        #pragma unroll
        for (int ks = 0; ks < 4; ks++) {
            #pragma unroll
            for (int hh = 0; hh < 2; hh++) {
                int k = ks*16 + 2*t4 + 8*hh;
                __nv_bfloat162 pp = __floats2bfloat162_rn(cvec[k], cvec[k+1]);
                cs[ks*2+hh] = *(uint32_t*)&pp;
            }
        }

        float mrun = -1e30f;
        tt_tile<8>(0,   0, su, sb, cs, redf, rowm, colm, mrun, warp, lane);
        tt_tile<8>(1,  64, su, sb, cs, redf, rowm, colm, mrun, warp, lane);
        tt_tile<8>(2, 128, su, sb, cs, redf, rowm, colm, mrun, warp, lane);
        tt_tile<2>(3, 192, su, sb, cs, redf, rowm, colm, mrun, warp, lane);

        float zs = 0.f;
        for (int i = tid; i < TQ; i += TT_THREADS) zs += rowm[i];
        float Ztot = block_reduce_sum(zs, redf);
        float inv = 1.f / Ztot;

        int d = tid & 63, ch = tid >> 6;
        float accz = 0.f;
        for (int s = ch; s < TQ; s += 4) {
            accz += rowm[s] * __bfloat162float(smD[s*64 + d]);
            accz += colm[s] * __bfloat162float(smE[s*64 + d]);
        }
        scr[tid] = accz;
        __syncthreads();
        if (ch == 0) {
            float tot = scr[d] + scr[64 + d] + scr[128 + d] + scr[192 + d];
            Z[((size_t)(b*TQ + q))*DIMM + hoff + d] = tot * inv;
        }
        __syncthreads();
    }
}

// ---------------- classifier head (in-block K split) ----------------
__global__ void head_kernel(const float* __restrict__ XN, const float* __restrict__ W,
                            const float* __restrict__ bias, float* __restrict__ out) {
    __shared__ float sacc[256];
    int tid = threadIdx.x;
    int c = tid & 63, kc = tid >> 6;
    int n = blockIdx.x * 64 + c;
    int b = blockIdx.y;
    const float* x = XN + (size_t)b * TQ * DIMM;
    float acc = 0.f;
    if (n < NCLS) {
        #pragma unroll 8
        for (int i = 0; i < 64; i++) {
            int k = kc*64 + i;
            acc += x[k] * W[(size_t)k*NCLS + n];
        }
    }
    sacc[tid] = acc;
    __syncthreads();
    if (kc == 0 && n < NCLS)
        out[(size_t)b*NCLS + n] = sacc[c] + sacc[64 + c] + sacc[128 + c] + sacc[192 + c] + bias[n];
}

// ---------------- host launch ----------------
extern "C" void kernel_launch(void* const* d_in, const int* in_sizes, int n_in,
                              void* d_out, int out_size) {
    const float* img         = (const float*)d_in[0];
    const float* patch_ln1_g = (const float*)d_in[1];
    const float* patch_ln1_b = (const float*)d_in[2];
    const float* patch_w     = (const float*)d_in[3];
    const float* patch_b     = (const float*)d_in[4];
    const float* patch_ln2_g = (const float*)d_in[5];
    const float* patch_ln2_b = (const float*)d_in[6];
    const float* pos_emb     = (const float*)d_in[7];
    const float* cls_token   = (const float*)d_in[8];
    const float* attn_ln_g   = (const float*)d_in[9];
    const float* attn_ln_b   = (const float*)d_in[10];
    const float* w_abcde     = (const float*)d_in[11];
    const float* b_abcde     = (const float*)d_in[12];
    const float* w_out       = (const float*)d_in[13];
    const float* b_out       = (const float*)d_in[14];
    const float* ff_ln_g     = (const float*)d_in[15];
    const float* ff_ln_b     = (const float*)d_in[16];
    const float* ff_w1       = (const float*)d_in[17];
    const float* ff_b1       = (const float*)d_in[18];
    const float* ff_w2       = (const float*)d_in[19];
    const float* ff_b2       = (const float*)d_in[20];
    const float* final_ln_g  = (const float*)d_in[21];
    const float* final_ln_b  = (const float*)d_in[22];
    const float* head_w      = (const float*)d_in[23];
    const float* head_b      = (const float*)d_in[24];
    float* out = (float*)d_out;

    float *pn, *t1, *x, *xn, *ab, *z, *hb, *pp;
    cudaGetSymbolAddress((void**)&pn, g_pn);
    cudaGetSymbolAddress((void**)&t1, g_t1);
    cudaGetSymbolAddress((void**)&x,  g_x);
    cudaGetSymbolAddress((void**)&xn, g_xn);
    cudaGetSymbolAddress((void**)&ab, g_ab);
    cudaGetSymbolAddress((void**)&z,  g_z);
    cudaGetSymbolAddress((void**)&hb, g_h);
    cudaGetSymbolAddress((void**)&pp, g_part);

    cudaFuncSetAttribute(tritt_mma_kernel,
                         cudaFuncAttributeMaxDynamicSharedMemorySize, SMB_TOTAL);

    const int MN = MROWS*DIMM;           // 394*256
    const int MN_P = BATCH*NPATCH*DIMM;  // 392*256

    // patch embed (split-K 3 over K=768)
    gather_kernel<<<BATCH*NPATCH, 256>>>(img);
    ln_kernel<<<BATCH*NPATCH, 256>>>(pn, patch_ln1_g, patch_ln1_b, pn, PATCH_DIM);
    gemm_part_kernel<<<dim3(4, 7, 3), 256>>>(pn, patch_w, pp, BATCH*NPATCH, DIMM, 256);
    combine_kernel<<<(MN_P + 255)/256, 256>>>(pp, 3, patch_b, nullptr, t1, BATCH*NPATCH, DIMM);
    assemble_kernel<<<MROWS, 256>>>(t1, patch_ln2_g, patch_ln2_b, cls_token, pos_emb, x);

    for (int L = 0; L < 2; L++) {
        ln_kernel<<<MROWS, 256>>>(x, attn_ln_g + L*DIMM, attn_ln_b + L*DIMM, xn, DIMM);
        gemm_kernel<0><<<dim3(20, 7), 256>>>(xn, w_abcde + (size_t)L*DIMM*FIVE,
                                             b_abcde + L*FIVE, nullptr, ab,
                                             MROWS, DIMM, FIVE);
        tritt_mma_kernel<<<BATCH*HEADS*NQCHUNK, TT_THREADS, SMB_TOTAL>>>(ab, z);
        // out proj: split-K 2 over K=256, residual fused in combine
        gemm_part_kernel<<<dim3(4, 7, 2), 256>>>(z, w_out + (size_t)L*DIMM*DIMM,
                                                 pp, MROWS, DIMM, 128);
        combine_kernel<<<(MN + 255)/256, 256>>>(pp, 2, b_out + L*DIMM, x, x, MROWS, DIMM);
        ln_kernel<<<MROWS, 256>>>(x, ff_ln_g + L*DIMM, ff_ln_b + L*DIMM, xn, DIMM);
        gemm_kernel<1><<<dim3(16, 7), 256>>>(xn, ff_w1 + (size_t)L*DIMM*MLPD,
                                             ff_b1 + L*MLPD, nullptr, hb,
                                             MROWS, DIMM, MLPD);
        // ff2: split-K 4 over K=1024, residual fused in combine
        gemm_part_kernel<<<dim3(4, 7, 4), 256>>>(hb, ff_w2 + (size_t)L*MLPD*DIMM,
                                                 pp, MROWS, DIMM, 256);
        combine_kernel<<<(MN + 255)/256, 256>>>(pp, 4, ff_b2 + L*DIMM, x, x, MROWS, DIMM);
    }

    ln_kernel<<<MROWS, 256>>>(x, final_ln_g, final_ln_b, xn, DIMM);
    head_kernel<<<dim3(16, BATCH), 256>>>(xn, head_w, head_b, out);
}

// round 7
// speedup vs baseline: 1.0777x; 1.0777x over previous
#include <cuda_runtime.h>
#include <cuda_bf16.h>
#include <cstdint>
#include <math.h>

// ---------------- problem constants ----------------
#define BATCH     2
#define TQ        197
#define DIMM      256
#define HEADS     4
#define DH        64
#define FIVE      1280
#define MLPD      1024
#define NCLS      1000
#define PATCH_DIM 768
#define NPATCH    196
#define MROWS     (BATCH*TQ)     // 394

// ---------------- tritt v3 constants ----------------
#define TT_THREADS 256
#define MPAD       256
#define BROWS      208
#define QB         4
#define NQCHUNK    50            // ceil(197/4)

// dynamic smem byte offsets (A/B 1024-aligned for swizzle)
#define SMB_RED    0                        // 32 floats
#define SMB_CVEC   128                      // 64 floats
#define SMB_ROWM   384                      // 208 floats
#define SMB_COLM   1216                     // 208 floats
#define SMB_SCR    2048                     // 256 floats
#define SMB_A      3072                     // 256 x 128B bf16 swizzled
#define SMB_B      (SMB_A + MPAD*128)       // 35840: 208 x 128B
#define SMB_TOTAL  (SMB_B + BROWS*128)      // 62464 bytes

__device__ __forceinline__ uint32_t swz(uint32_t off) {
    return off ^ ((off >> 3) & 0x70);
}

// ---------------- device scratch ----------------
__device__ float g_pn[BATCH*NPATCH*PATCH_DIM];
__device__ float g_x[MROWS*DIMM];
__device__ float g_xn[MROWS*DIMM];
__device__ float g_ab[MROWS*FIVE];
__device__ float g_z[MROWS*DIMM];
__device__ float g_h[MROWS*MLPD];
__device__ float g_part[4*MROWS*DIMM];   // split-K partials (max 4 slabs)

// ---------------- PTX helpers ----------------
__device__ __forceinline__ uint32_t smem_u32(const void* p) {
    uint32_t a;
    asm("{ .reg .u64 t; cvta.to.shared.u64 t, %1; cvt.u32.u64 %0, t; }" : "=r"(a) : "l"(p));
    return a;
}
__device__ __forceinline__ void ldm_x4(uint32_t addr, uint32_t* r) {
    asm volatile("ldmatrix.sync.aligned.m8n8.x4.shared.b16 {%0,%1,%2,%3}, [%4];"
                 : "=r"(r[0]), "=r"(r[1]), "=r"(r[2]), "=r"(r[3]) : "r"(addr));
}
__device__ __forceinline__ void ldm_x2(uint32_t addr, uint32_t* r) {
    asm volatile("ldmatrix.sync.aligned.m8n8.x2.shared.b16 {%0,%1}, [%2];"
                 : "=r"(r[0]), "=r"(r[1]) : "r"(addr));
}
__device__ __forceinline__ void mma16816(float* c, const uint32_t* a, const uint32_t* b) {
    asm volatile("mma.sync.aligned.m16n8k16.row.col.f32.bf16.bf16.f32 "
                 "{%0,%1,%2,%3}, {%4,%5,%6,%7}, {%8,%9}, {%0,%1,%2,%3};"
                 : "+f"(c[0]), "+f"(c[1]), "+f"(c[2]), "+f"(c[3])
                 : "r"(a[0]), "r"(a[1]), "r"(a[2]), "r"(a[3]), "r"(b[0]), "r"(b[1]));
}
__device__ __forceinline__ uint32_t hmul2u(uint32_t a, uint32_t b) {
    __nv_bfloat162 x = *(__nv_bfloat162*)&a, y = *(__nv_bfloat162*)&b;
    __nv_bfloat162 z = __hmul2(x, y);
    return *(uint32_t*)&z;
}

// ---------------- reductions (blockDim == 256, 8 warps) ----------------
__device__ __forceinline__ float block_reduce_sum(float v, float* red) {
    #pragma unroll
    for (int o = 16; o > 0; o >>= 1) v += __shfl_xor_sync(0xffffffffu, v, o);
    if ((threadIdx.x & 31) == 0) red[threadIdx.x >> 5] = v;
    __syncthreads();
    if (threadIdx.x < 32) {
        float r = (threadIdx.x < 8) ? red[threadIdx.x] : 0.f;
        #pragma unroll
        for (int o = 4; o > 0; o >>= 1) r += __shfl_xor_sync(0xffffffffu, r, o);
        if (threadIdx.x == 0) red[0] = r;
    }
    __syncthreads();
    float out = red[0];
    __syncthreads();
    return out;
}

// ---------------- fused patch gather + LN1 ----------------
__global__ void gather_ln_kernel(const float* __restrict__ img,
                                 const float* __restrict__ g, const float* __restrict__ bv) {
    __shared__ float red[32];
    int row = blockIdx.x;
    int b = row / NPATCH, pidx = row % NPATCH;
    int gh = pidx / 14, gw = pidx % 14;
    float v[3];
    #pragma unroll
    for (int r = 0; r < 3; r++) {
        int j = threadIdx.x + r*256;
        int p1 = j / 48, rem = j % 48, p2 = rem / 3, c = rem % 3;
        v[r] = img[(((size_t)b*3 + c)*224 + gh*16 + p1)*224 + gw*16 + p2];
    }
    float s = v[0] + v[1] + v[2];
    float mean = block_reduce_sum(s, red) * (1.f/PATCH_DIM);
    float vs = 0.f;
    #pragma unroll
    for (int r = 0; r < 3; r++) { float d = v[r]-mean; vs += d*d; }
    float var = block_reduce_sum(vs, red) * (1.f/PATCH_DIM);
    float inv = rsqrtf(var + 1e-5f);
    #pragma unroll
    for (int r = 0; r < 3; r++) {
        int j = threadIdx.x + r*256;
        g_pn[(size_t)row*PATCH_DIM + j] = (v[r]-mean)*inv*g[j] + bv[j];
    }
}

// ---------------- generic LayerNorm (width 256, thread per col) ----------------
__global__ void ln_kernel(const float* __restrict__ X, const float* __restrict__ g,
                          const float* __restrict__ bv, float* __restrict__ Y) {
    __shared__ float red[32];
    int row = blockIdx.x;
    int j = threadIdx.x;
    float v = X[(size_t)row*DIMM + j];
    float mean = block_reduce_sum(v, red) * (1.f/DIMM);
    float d = v - mean;
    float var = block_reduce_sum(d*d, red) * (1.f/DIMM);
    float inv = rsqrtf(var + 1e-5f);
    Y[(size_t)row*DIMM + j] = d*inv*g[j] + bv[j];
}

// ---------------- fused assemble: patch combine + LN2 + cls/pos + attn LN0 ----------------
__global__ void assemble_fused_kernel(const float* __restrict__ P,
                                      const float* __restrict__ pbias,
                                      const float* __restrict__ g2, const float* __restrict__ b2,
                                      const float* __restrict__ cls, const float* __restrict__ pos,
                                      const float* __restrict__ ga, const float* __restrict__ ba,
                                      float* __restrict__ X, float* __restrict__ XN) {
    __shared__ float red[32];
    int row = blockIdx.x;
    int b = row / TQ, t = row % TQ;
    int j = threadIdx.x;
    float xv;
    if (t == 0) {
        xv = cls[j] + pos[j];
    } else {
        int prow = b*NPATCH + t - 1;
        float v = pbias[j];
        #pragma unroll
        for (int s = 0; s < 3; s++)
            v += P[(size_t)s*BATCH*NPATCH*DIMM + (size_t)prow*DIMM + j];
        float mean = block_reduce_sum(v, red) * (1.f/DIMM);
        float d = v - mean;
        float var = block_reduce_sum(d*d, red) * (1.f/DIMM);
        float inv = rsqrtf(var + 1e-5f);
        xv = d*inv*g2[j] + b2[j] + pos[t*DIMM + j];
    }
    X[(size_t)row*DIMM + j] = xv;
    // attn LN (layer 0)
    float mean = block_reduce_sum(xv, red) * (1.f/DIMM);
    float d = xv - mean;
    float var = block_reduce_sum(d*d, red) * (1.f/DIMM);
    float inv = rsqrtf(var + 1e-5f);
    XN[(size_t)row*DIMM + j] = d*inv*ga[j] + ba[j];
}

// ---------------- combine split-K + bias + residual -> X, then LN -> XN ----------------
__global__ void combine_ln_kernel(const float* __restrict__ P, int ns,
                                  const float* __restrict__ bias, const float* __restrict__ R,
                                  const float* __restrict__ g, const float* __restrict__ bv,
                                  float* __restrict__ X, float* __restrict__ XN) {
    __shared__ float red[32];
    int row = blockIdx.x;
    int j = threadIdx.x;
    float v = bias[j] + R[(size_t)row*DIMM + j];
    for (int s = 0; s < ns; s++)
        v += P[(size_t)s*MROWS*DIMM + (size_t)row*DIMM + j];
    X[(size_t)row*DIMM + j] = v;
    float mean = block_reduce_sum(v, red) * (1.f/DIMM);
    float d = v - mean;
    float var = block_reduce_sum(d*d, red) * (1.f/DIMM);
    float inv = rsqrtf(var + 1e-5f);
    XN[(size_t)row*DIMM + j] = d*inv*g[j] + bv[j];
}

// ---------------- generic fp32 GEMM ----------------
__device__ __forceinline__ float gelu_exact(float v) {
    return 0.5f * v * (1.f + erff(v * 0.70710678118654752f));
}

template<int ACT>
__global__ void gemm_kernel(const float* __restrict__ A, const float* __restrict__ W,
                            const float* __restrict__ bias, const float* __restrict__ R,
                            float* __restrict__ C, int M, int K, int N) {
    __shared__ float As[16][68];
    __shared__ float Ws[16][68];
    int tid = threadIdx.x;
    int tx = tid & 15, ty = tid >> 4;
    int m0 = blockIdx.y * 64, n0 = blockIdx.x * 64;
    float acc[4][4];
    #pragma unroll
    for (int i = 0; i < 4; i++)
        #pragma unroll
        for (int j = 0; j < 4; j++) acc[i][j] = 0.f;

    int am = tid >> 2, ak = (tid & 3) << 2;
    int wk = tid >> 4, wn = (tid & 15) << 2;

    for (int k0 = 0; k0 < K; k0 += 16) {
        float4 av = make_float4(0.f, 0.f, 0.f, 0.f);
        if (m0 + am < M)
            av = *(const float4*)&A[(size_t)(m0 + am)*K + k0 + ak];
        As[ak + 0][am] = av.x; As[ak + 1][am] = av.y;
        As[ak + 2][am] = av.z; As[ak + 3][am] = av.w;
        #pragma unroll
        for (int e = 0; e < 4; e++) {
            int n = n0 + wn + e;
            Ws[wk][wn + e] = (n < N) ? W[(size_t)(k0 + wk)*N + n] : 0.f;
        }
        __syncthreads();
        #pragma unroll
        for (int k = 0; k < 16; k++) {
            float a0 = As[k][ty*4+0], a1 = As[k][ty*4+1];
            float a2 = As[k][ty*4+2], a3 = As[k][ty*4+3];
            float w0 = Ws[k][tx*4+0], w1 = Ws[k][tx*4+1];
            float w2 = Ws[k][tx*4+2], w3 = Ws[k][tx*4+3];
            acc[0][0] += a0*w0; acc[0][1] += a0*w1; acc[0][2] += a0*w2; acc[0][3] += a0*w3;
            acc[1][0] += a1*w0; acc[1][1] += a1*w1; acc[1][2] += a1*w2; acc[1][3] += a1*w3;
            acc[2][0] += a2*w0; acc[2][1] += a2*w1; acc[2][2] += a2*w2; acc[2][3] += a2*w3;
            acc[3][0] += a3*w0; acc[3][1] += a3*w1; acc[3][2] += a3*w2; acc[3][3] += a3*w3;
        }
        __syncthreads();
    }
    #pragma unroll
    for (int i = 0; i < 4; i++) {
        int m = m0 + ty*4 + i;
        if (m >= M) continue;
        #pragma unroll
        for (int j = 0; j < 4; j++) {
            int n = n0 + tx*4 + j;
            if (n >= N) continue;
            float v = acc[i][j] + bias[n];
            if (ACT == 1) v = gelu_exact(v);
            if (R != nullptr) v += R[(size_t)m*N + n];
            C[(size_t)m*N + n] = v;
        }
    }
}

// ---------------- split-K GEMM: partial slabs ----------------
__global__ void gemm_part_kernel(const float* __restrict__ A, const float* __restrict__ W,
                                 float* __restrict__ P, int M, int N, int klen) {
    __shared__ float As[16][68];
    __shared__ float Ws[16][68];
    int tid = threadIdx.x;
    int tx = tid & 15, ty = tid >> 4;
    int m0 = blockIdx.y * 64, n0 = blockIdx.x * 64;
    int kstart = blockIdx.z * klen;
    float* C = P + (size_t)blockIdx.z * M * N;
    float acc[4][4];
    #pragma unroll
    for (int i = 0; i < 4; i++)
        #pragma unroll
        for (int j = 0; j < 4; j++) acc[i][j] = 0.f;

    int am = tid >> 2, ak = (tid & 3) << 2;
    int wk = tid >> 4, wn = (tid & 15) << 2;

    for (int k0 = kstart; k0 < kstart + klen; k0 += 16) {
        float4 av = make_float4(0.f, 0.f, 0.f, 0.f);
        if (m0 + am < M)
            av = *(const float4*)&A[(size_t)(m0 + am)*(klen*gridDim.z) + k0 + ak];
        As[ak + 0][am] = av.x; As[ak + 1][am] = av.y;
        As[ak + 2][am] = av.z; As[ak + 3][am] = av.w;
        #pragma unroll
        for (int e = 0; e < 4; e++) {
            int n = n0 + wn + e;
            Ws[wk][wn + e] = (n < N) ? W[(size_t)(k0 + wk)*N + n] : 0.f;
        }
        __syncthreads();
        #pragma unroll
        for (int k = 0; k < 16; k++) {
            float a0 = As[k][ty*4+0], a1 = As[k][ty*4+1];
            float a2 = As[k][ty*4+2], a3 = As[k][ty*4+3];
            float w0 = Ws[k][tx*4+0], w1 = Ws[k][tx*4+1];
            float w2 = Ws[k][tx*4+2], w3 = Ws[k][tx*4+3];
            acc[0][0] += a0*w0; acc[0][1] += a0*w1; acc[0][2] += a0*w2; acc[0][3] += a0*w3;
            acc[1][0] += a1*w0; acc[1][1] += a1*w1; acc[1][2] += a1*w2; acc[1][3] += a1*w3;
            acc[2][0] += a2*w0; acc[2][1] += a2*w1; acc[2][2] += a2*w2; acc[2][3] += a2*w3;
            acc[3][0] += a3*w0; acc[3][1] += a3*w1; acc[3][2] += a3*w2; acc[3][3] += a3*w3;
        }
        __syncthreads();
    }
    #pragma unroll
    for (int i = 0; i < 4; i++) {
        int m = m0 + ty*4 + i;
        if (m >= M) continue;
        #pragma unroll
        for (int j = 0; j < 4; j++) {
            int n = n0 + tx*4 + j;
            if (n >= N) continue;
            C[(size_t)m*N + n] = acc[i][j];
        }
    }
}

// ---------------- tritt v3 tile: mma + exp (no max) + marginal atomics ----------------
template<int NJ>
__device__ __forceinline__ void tt_tile3(
    int tbase, uint32_t su, uint32_t sb, const uint32_t* cs,
    float* rowm, float* colm, int warp, int lane)
{
    const int g = lane >> 2, t4 = lane & 3;

    float acc[2][NJ][4];
    #pragma unroll
    for (int mc = 0; mc < 2; mc++)
        #pragma unroll
        for (int j = 0; j < NJ; j++)
            #pragma unroll
            for (int r = 0; r < 4; r++) acc[mc][j][r] = 0.f;

    const int arow = (lane & 7) + ((lane >> 3) & 1) * 8;
    const int akb  = (lane >> 4) << 4;
    const int l2   = lane & 15;
    const int brow = l2 & 7;
    const int bkb  = (l2 >> 3) << 4;

    #pragma unroll
    for (int ks = 0; ks < 4; ks++) {
        uint32_t a[2][4];
        #pragma unroll
        for (int mc = 0; mc < 2; mc++) {
            int row = warp*32 + mc*16 + arow;
            ldm_x4(su + swz((uint32_t)(row*128 + ks*32 + akb)), a[mc]);
            a[mc][0] = hmul2u(a[mc][0], cs[ks*2+0]);
            a[mc][1] = hmul2u(a[mc][1], cs[ks*2+0]);
            a[mc][2] = hmul2u(a[mc][2], cs[ks*2+1]);
            a[mc][3] = hmul2u(a[mc][3], cs[ks*2+1]);
        }
        uint32_t b[NJ][2];
        #pragma unroll
        for (int j = 0; j < NJ; j++) {
            int row = tbase + j*8 + brow;
            ldm_x2(sb + swz((uint32_t)(row*128 + ks*32 + bkb)), b[j]);
        }
        #pragma unroll
        for (int mc = 0; mc < 2; mc++)
            #pragma unroll
            for (int j = 0; j < NJ; j++)
                mma16816(acc[mc][j], a[mc], b[j]);
    }

    bool vr[4];
    #pragma unroll
    for (int i = 0; i < 4; i++)
        vr[i] = (warp*32 + (i >> 1)*16 + (i & 1)*8 + g) < TQ;

    // exp (no max subtraction — |s| << 1 by construction) + row sums
    float rsum[4] = {0.f, 0.f, 0.f, 0.f};
    #pragma unroll
    for (int mc = 0; mc < 2; mc++) {
        #pragma unroll
        for (int j = 0; j < NJ; j++) {
            int c0 = tbase + j*8 + 2*t4;
            bool vc0 = c0 < TQ, vc1 = (c0 + 1) < TQ;
            float e0 = (vr[mc*2]   && vc0) ? __expf(acc[mc][j][0]) : 0.f;
            float e1 = (vr[mc*2]   && vc1) ? __expf(acc[mc][j][1]) : 0.f;
            float e2 = (vr[mc*2+1] && vc0) ? __expf(acc[mc][j][2]) : 0.f;
            float e3 = (vr[mc*2+1] && vc1) ? __expf(acc[mc][j][3]) : 0.f;
            acc[mc][j][0] = e0; acc[mc][j][1] = e1;
            acc[mc][j][2] = e2; acc[mc][j][3] = e3;
            rsum[mc*2]   += e0 + e1;
            rsum[mc*2+1] += e2 + e3;
        }
    }
    #pragma unroll
    for (int i = 0; i < 4; i++) {
        rsum[i] += __shfl_xor_sync(0xffffffffu, rsum[i], 1);
        rsum[i] += __shfl_xor_sync(0xffffffffu, rsum[i], 2);
    }
    if (t4 == 0) {
        #pragma unroll
        for (int i = 0; i < 4; i++) {
            int r = warp*32 + (i >> 1)*16 + (i & 1)*8 + g;
            if (r < TQ) atomicAdd(&rowm[r], rsum[i]);
        }
    }
    #pragma unroll
    for (int j = 0; j < NJ; j++) {
        float cs0 = acc[0][j][0] + acc[0][j][2] + acc[1][j][0] + acc[1][j][2];
        float cs1 = acc[0][j][1] + acc[0][j][3] + acc[1][j][1] + acc[1][j][3];
        #pragma unroll
        for (int o = 4; o <= 16; o <<= 1) {
            cs0 += __shfl_xor_sync(0xffffffffu, cs0, o);
            cs1 += __shfl_xor_sync(0xffffffffu, cs1, o);
        }
        if (g == 0) {
            int c0 = tbase + j*8 + 2*t4;
            if (c0 < TQ && cs0 != 0.f) atomicAdd(&colm[c0], cs0);
            if (c0 + 1 < TQ && cs1 != 0.f) atomicAdd(&colm[c0 + 1], cs1);
        }
    }
}

// ---------------- trittention v3: one CTA per (b, h, q-block of 4) ----------------
__global__ __launch_bounds__(TT_THREADS, 2)
void tritt_mma_kernel(const float* __restrict__ abcde, float* __restrict__ Z) {
    extern __shared__ char smc[];
    float* redf = (float*)(smc + SMB_RED);
    float* cvec = (float*)(smc + SMB_CVEC);
    float* rowm = (float*)(smc + SMB_ROWM);
    float* colm = (float*)(smc + SMB_COLM);
    float* scr  = (float*)(smc + SMB_SCR);
    uint32_t su = smem_u32(smc + SMB_A);
    uint32_t sb = smem_u32(smc + SMB_B);

    const int tid = threadIdx.x;
    const int warp = tid >> 5, lane = tid & 31;
    const int t4 = lane & 3;

    int pair = blockIdx.x / NQCHUNK;
    int qc = blockIdx.x % NQCHUNK;
    int b = pair >> 2, h = pair & 3;
    const float* base = abcde + (size_t)b * TQ * FIVE;
    const int hoff = h * DH;
    int q0 = qc * QB;
    int nq = (TQ - q0 < QB) ? (TQ - q0) : QB;

    // ---- per-CTA setup: A raw bf16, B bf16 ----
    for (int idx = tid; idx < MPAD*32; idx += TT_THREADS) {
        int s = idx >> 5, dp = (idx & 31) << 1;
        uint32_t val = 0u;
        if (s < TQ) {
            float2 av = *(const float2*)&base[(size_t)s*FIVE + hoff + dp];
            __nv_bfloat162 pp = __floats2bfloat162_rn(av.x, av.y);
            val = *(uint32_t*)&pp;
        }
        *(uint32_t*)(smc + SMB_A + swz((uint32_t)(s*128 + dp*2))) = val;
    }
    for (int idx = tid; idx < BROWS*32; idx += TT_THREADS) {
        int t = idx >> 5, dp = (idx & 31) << 1;
        uint32_t val = 0u;
        if (t < TQ) {
            float2 bv = *(const float2*)&base[(size_t)t*FIVE + DIMM + hoff + dp];
            __nv_bfloat162 pp = __floats2bfloat162_rn(bv.x, bv.y);
            val = *(uint32_t*)&pp;
        }
        *(uint32_t*)(smc + SMB_B + swz((uint32_t)(t*128 + dp*2))) = val;
    }
    __syncthreads();

    // ---- per-q loop ----
    for (int iq = 0; iq < nq; iq++) {
        int q = q0 + iq;
        if (tid < DH)
            cvec[tid] = base[(size_t)q*FIVE + 2*DIMM + hoff + tid] * (1.0f/DH);
        if (tid < BROWS) { rowm[tid] = 0.f; colm[tid] = 0.f; }
        __syncthreads();

        uint32_t cs[8];
        #pragma unroll
        for (int ks = 0; ks < 4; ks++) {
            #pragma unroll
            for (int hh = 0; hh < 2; hh++) {
                int k = ks*16 + 2*t4 + 8*hh;
                __nv_bfloat162 pp = __floats2bfloat162_rn(cvec[k], cvec[k+1]);
                cs[ks*2+hh] = *(uint32_t*)&pp;
            }
        }

        // no barriers between tiles — atomics only
        tt_tile3<8>(  0, su, sb, cs, rowm, colm, warp, lane);
        tt_tile3<8>( 64, su, sb, cs, rowm, colm, warp, lane);
        tt_tile3<8>(128, su, sb, cs, rowm, colm, warp, lane);
        tt_tile3<2>(192, su, sb, cs, rowm, colm, warp, lane);
        __syncthreads();

        float zs = 0.f;
        for (int i = tid; i < TQ; i += TT_THREADS) zs += rowm[i];
        float Ztot = block_reduce_sum(zs, redf);
        float inv = 1.f / Ztot;

        // epilogue: fp32 D/E from gmem (L2-resident)
        int d = tid & 63, ch = tid >> 6;
        float accz = 0.f;
        for (int s = ch; s < TQ; s += 4) {
            accz += rowm[s] * base[(size_t)s*FIVE + 3*DIMM + hoff + d];
            accz += colm[s] * base[(size_t)s*FIVE + 4*DIMM + hoff + d];
        }
        scr[tid] = accz;
        __syncthreads();
        if (ch == 0) {
            float tot = scr[d] + scr[64 + d] + scr[128 + d] + scr[192 + d];
            Z[((size_t)(b*TQ + q))*DIMM + hoff + d] = tot * inv;
        }
        __syncthreads();
    }
}

// ---------------- classifier head (in-block K split; XN already final-LN'd) ----------------
__global__ void head_kernel(const float* __restrict__ XN, const float* __restrict__ W,
                            const float* __restrict__ bias, float* __restrict__ out) {
    __shared__ float sacc[256];
    int tid = threadIdx.x;
    int c = tid & 63, kc = tid >> 6;
    int n = blockIdx.x * 64 + c;
    int b = blockIdx.y;
    const float* x = XN + (size_t)b * TQ * DIMM;   // token 0
    float acc = 0.f;
    if (n < NCLS) {
        #pragma unroll 8
        for (int i = 0; i < 64; i++) {
            int k = kc*64 + i;
            acc += x[k] * W[(size_t)k*NCLS + n];
        }
    }
    sacc[tid] = acc;
    __syncthreads();
    if (kc == 0 && n < NCLS)
        out[(size_t)b*NCLS + n] = sacc[c] + sacc[64 + c] + sacc[128 + c] + sacc[192 + c] + bias[n];
}

// ---------------- host launch ----------------
extern "C" void kernel_launch(void* const* d_in, const int* in_sizes, int n_in,
                              void* d_out, int out_size) {
    const float* img         = (const float*)d_in[0];
    const float* patch_ln1_g = (const float*)d_in[1];
    const float* patch_ln1_b = (const float*)d_in[2];
    const float* patch_w     = (const float*)d_in[3];
    const float* patch_b     = (const float*)d_in[4];
    const float* patch_ln2_g = (const float*)d_in[5];
    const float* patch_ln2_b = (const float*)d_in[6];
    const float* pos_emb     = (const float*)d_in[7];
    const float* cls_token   = (const float*)d_in[8];
    const float* attn_ln_g   = (const float*)d_in[9];
    const float* attn_ln_b   = (const float*)d_in[10];
    const float* w_abcde     = (const float*)d_in[11];
    const float* b_abcde     = (const float*)d_in[12];
    const float* w_out       = (const float*)d_in[13];
    const float* b_out       = (const float*)d_in[14];
    const float* ff_ln_g     = (const float*)d_in[15];
    const float* ff_ln_b     = (const float*)d_in[16];
    const float* ff_w1       = (const float*)d_in[17];
    const float* ff_b1       = (const float*)d_in[18];
    const float* ff_w2       = (const float*)d_in[19];
    const float* ff_b2       = (const float*)d_in[20];
    const float* final_ln_g  = (const float*)d_in[21];
    const float* final_ln_b  = (const float*)d_in[22];
    const float* head_w      = (const float*)d_in[23];
    const float* head_b      = (const float*)d_in[24];
    float* out = (float*)d_out;

    float *pn, *x, *xn, *ab, *z, *hb, *pp;
    cudaGetSymbolAddress((void**)&pn, g_pn);
    cudaGetSymbolAddress((void**)&x,  g_x);
    cudaGetSymbolAddress((void**)&xn, g_xn);
    cudaGetSymbolAddress((void**)&ab, g_ab);
    cudaGetSymbolAddress((void**)&z,  g_z);
    cudaGetSymbolAddress((void**)&hb, g_h);
    cudaGetSymbolAddress((void**)&pp, g_part);

    cudaFuncSetAttribute(tritt_mma_kernel,
                         cudaFuncAttributeMaxDynamicSharedMemorySize, SMB_TOTAL);

    // patch embed: gather+LN1, split-K GEMM, fused combine+LN2+pos+attnLN0
    gather_ln_kernel<<<BATCH*NPATCH, 256>>>(img, patch_ln1_g, patch_ln1_b);
    gemm_part_kernel<<<dim3(4, 7, 3), 256>>>(pn, patch_w, pp, BATCH*NPATCH, DIMM, 256);
    assemble_fused_kernel<<<MROWS, 256>>>(pp, patch_b, patch_ln2_g, patch_ln2_b,
                                          cls_token, pos_emb, attn_ln_g, attn_ln_b, x, xn);

    for (int L = 0; L < 2; L++) {
        gemm_kernel<0><<<dim3(20, 7), 256>>>(xn, w_abcde + (size_t)L*DIMM*FIVE,
                                             b_abcde + L*FIVE, nullptr, ab,
                                             MROWS, DIMM, FIVE);
        tritt_mma_kernel<<<BATCH*HEADS*NQCHUNK, TT_THREADS, SMB_TOTAL>>>(ab, z);
        // out proj: direct GEMM, bias + residual fused
        gemm_kernel<0><<<dim3(4, 7), 256>>>(z, w_out + (size_t)L*DIMM*DIMM,
                                            b_out + L*DIMM, x, x,
                                            MROWS, DIMM, DIMM);
        ln_kernel<<<MROWS, 256>>>(x, ff_ln_g + L*DIMM, ff_ln_b + L*DIMM, xn);
        gemm_kernel<1><<<dim3(16, 7), 256>>>(xn, ff_w1 + (size_t)L*DIMM*MLPD,
                                             ff_b1 + L*MLPD, nullptr, hb,
                                             MROWS, DIMM, MLPD);
        gemm_part_kernel<<<dim3(4, 7, 4), 256>>>(hb, ff_w2 + (size_t)L*MLPD*DIMM,
                                                 pp, MROWS, DIMM, 256);
        // combine + next LN: attn LN of L+1, or final LN before head
        const float* ng = (L == 0) ? (attn_ln_g + DIMM) : final_ln_g;
        const float* nb = (L == 0) ? (attn_ln_b + DIMM) : final_ln_b;
        combine_ln_kernel<<<MROWS, 256>>>(pp, 4, ff_b2 + L*DIMM, x, ng, nb, x, xn);
    }

    head_kernel<<<dim3(16, BATCH), 256>>>(xn, head_w, head_b, out);
}

// round 8
// speedup vs baseline: 1.1020x; 1.0225x over previous
#include <cuda_runtime.h>
#include <cuda_bf16.h>
#include <cstdint>
#include <math.h>

// ---------------- problem constants ----------------
#define BATCH     2
#define TQ        197
#define DIMM      256
#define HEADS     4
#define DH        64
#define FIVE      1280
#define MLPD      1024
#define NCLS      1000
#define PATCH_DIM 768
#define NPATCH    196
#define MROWS     (BATCH*TQ)     // 394

// ---------------- tritt v3 constants ----------------
#define TT_THREADS 256
#define MPAD       256
#define BROWS      208
#define QB         4
#define NQCHUNK    50            // ceil(197/4)

// dynamic smem byte offsets (A/B 1024-aligned for swizzle)
#define SMB_RED    0                        // 32 floats
#define SMB_CVEC   128                      // 64 floats
#define SMB_ROWM   384                      // 208 floats
#define SMB_COLM   1216                     // 208 floats
#define SMB_SCR    2048                     // 256 floats
#define SMB_A      3072                     // 256 x 128B bf16 swizzled
#define SMB_B      (SMB_A + MPAD*128)       // 35840: 208 x 128B
#define SMB_TOTAL  (SMB_B + BROWS*128)      // 62464 bytes

__device__ __forceinline__ uint32_t swz(uint32_t off) {
    return off ^ ((off >> 3) & 0x70);
}

// ---------------- device scratch ----------------
__device__ float g_pn[BATCH*NPATCH*PATCH_DIM];
__device__ float g_x[MROWS*DIMM];
__device__ float g_xn[MROWS*DIMM];
__device__ float g_ab[MROWS*FIVE];
__device__ float g_z[MROWS*DIMM];
__device__ float g_h[MROWS*MLPD];
__device__ float g_part[4*MROWS*DIMM];   // split-K partials (max 4 slabs)

// ---------------- PTX helpers ----------------
__device__ __forceinline__ uint32_t smem_u32(const void* p) {
    uint32_t a;
    asm("{ .reg .u64 t; cvta.to.shared.u64 t, %1; cvt.u32.u64 %0, t; }" : "=r"(a) : "l"(p));
    return a;
}
__device__ __forceinline__ void ldm_x4(uint32_t addr, uint32_t* r) {
    asm volatile("ldmatrix.sync.aligned.m8n8.x4.shared.b16 {%0,%1,%2,%3}, [%4];"
                 : "=r"(r[0]), "=r"(r[1]), "=r"(r[2]), "=r"(r[3]) : "r"(addr));
}
__device__ __forceinline__ void ldm_x2(uint32_t addr, uint32_t* r) {
    asm volatile("ldmatrix.sync.aligned.m8n8.x2.shared.b16 {%0,%1}, [%2];"
                 : "=r"(r[0]), "=r"(r[1]) : "r"(addr));
}
__device__ __forceinline__ void mma16816(float* c, const uint32_t* a, const uint32_t* b) {
    asm volatile("mma.sync.aligned.m16n8k16.row.col.f32.bf16.bf16.f32 "
                 "{%0,%1,%2,%3}, {%4,%5,%6,%7}, {%8,%9}, {%0,%1,%2,%3};"
                 : "+f"(c[0]), "+f"(c[1]), "+f"(c[2]), "+f"(c[3])
                 : "r"(a[0]), "r"(a[1]), "r"(a[2]), "r"(a[3]), "r"(b[0]), "r"(b[1]));
}
__device__ __forceinline__ void mma1688_tf32(float* c, const uint32_t* a, const uint32_t* b) {
    asm volatile("mma.sync.aligned.m16n8k8.row.col.f32.tf32.tf32.f32 "
                 "{%0,%1,%2,%3}, {%4,%5,%6,%7}, {%8,%9}, {%0,%1,%2,%3};"
                 : "+f"(c[0]), "+f"(c[1]), "+f"(c[2]), "+f"(c[3])
                 : "r"(a[0]), "r"(a[1]), "r"(a[2]), "r"(a[3]), "r"(b[0]), "r"(b[1]));
}
__device__ __forceinline__ uint32_t f2tf32(float f) {
    uint32_t r;
    asm("cvt.rna.tf32.f32 %0, %1;" : "=r"(r) : "f"(f));
    return r;
}
__device__ __forceinline__ uint32_t hmul2u(uint32_t a, uint32_t b) {
    __nv_bfloat162 x = *(__nv_bfloat162*)&a, y = *(__nv_bfloat162*)&b;
    __nv_bfloat162 z = __hmul2(x, y);
    return *(uint32_t*)&z;
}

// ---------------- reductions (blockDim == 256, 8 warps) ----------------
__device__ __forceinline__ float block_reduce_sum(float v, float* red) {
    #pragma unroll
    for (int o = 16; o > 0; o >>= 1) v += __shfl_xor_sync(0xffffffffu, v, o);
    if ((threadIdx.x & 31) == 0) red[threadIdx.x >> 5] = v;
    __syncthreads();
    if (threadIdx.x < 32) {
        float r = (threadIdx.x < 8) ? red[threadIdx.x] : 0.f;
        #pragma unroll
        for (int o = 4; o > 0; o >>= 1) r += __shfl_xor_sync(0xffffffffu, r, o);
        if (threadIdx.x == 0) red[0] = r;
    }
    __syncthreads();
    float out = red[0];
    __syncthreads();
    return out;
}

// ---------------- fused patch gather + LN1 ----------------
__global__ void gather_ln_kernel(const float* __restrict__ img,
                                 const float* __restrict__ g, const float* __restrict__ bv) {
    __shared__ float red[32];
    int row = blockIdx.x;
    int b = row / NPATCH, pidx = row % NPATCH;
    int gh = pidx / 14, gw = pidx % 14;
    float v[3];
    #pragma unroll
    for (int r = 0; r < 3; r++) {
        int j = threadIdx.x + r*256;
        int p1 = j / 48, rem = j % 48, p2 = rem / 3, c = rem % 3;
        v[r] = img[(((size_t)b*3 + c)*224 + gh*16 + p1)*224 + gw*16 + p2];
    }
    float s = v[0] + v[1] + v[2];
    float mean = block_reduce_sum(s, red) * (1.f/PATCH_DIM);
    float vs = 0.f;
    #pragma unroll
    for (int r = 0; r < 3; r++) { float d = v[r]-mean; vs += d*d; }
    float var = block_reduce_sum(vs, red) * (1.f/PATCH_DIM);
    float inv = rsqrtf(var + 1e-5f);
    #pragma unroll
    for (int r = 0; r < 3; r++) {
        int j = threadIdx.x + r*256;
        g_pn[(size_t)row*PATCH_DIM + j] = (v[r]-mean)*inv*g[j] + bv[j];
    }
}

// ---------------- generic LayerNorm (width 256, thread per col) ----------------
__global__ void ln_kernel(const float* __restrict__ X, const float* __restrict__ g,
                          const float* __restrict__ bv, float* __restrict__ Y) {
    __shared__ float red[32];
    int row = blockIdx.x;
    int j = threadIdx.x;
    float v = X[(size_t)row*DIMM + j];
    float mean = block_reduce_sum(v, red) * (1.f/DIMM);
    float d = v - mean;
    float var = block_reduce_sum(d*d, red) * (1.f/DIMM);
    float inv = rsqrtf(var + 1e-5f);
    Y[(size_t)row*DIMM + j] = d*inv*g[j] + bv[j];
}

// ---------------- fused assemble: patch combine + LN2 + cls/pos + attn LN0 ----------------
__global__ void assemble_fused_kernel(const float* __restrict__ P,
                                      const float* __restrict__ pbias,
                                      const float* __restrict__ g2, const float* __restrict__ b2,
                                      const float* __restrict__ cls, const float* __restrict__ pos,
                                      const float* __restrict__ ga, const float* __restrict__ ba,
                                      float* __restrict__ X, float* __restrict__ XN) {
    __shared__ float red[32];
    int row = blockIdx.x;
    int b = row / TQ, t = row % TQ;
    int j = threadIdx.x;
    float xv;
    if (t == 0) {
        xv = cls[j] + pos[j];
    } else {
        int prow = b*NPATCH + t - 1;
        float v = pbias[j];
        #pragma unroll
        for (int s = 0; s < 3; s++)
            v += P[(size_t)s*BATCH*NPATCH*DIMM + (size_t)prow*DIMM + j];
        float mean = block_reduce_sum(v, red) * (1.f/DIMM);
        float d = v - mean;
        float var = block_reduce_sum(d*d, red) * (1.f/DIMM);
        float inv = rsqrtf(var + 1e-5f);
        xv = d*inv*g2[j] + b2[j] + pos[t*DIMM + j];
    }
    X[(size_t)row*DIMM + j] = xv;
    float mean = block_reduce_sum(xv, red) * (1.f/DIMM);
    float d = xv - mean;
    float var = block_reduce_sum(d*d, red) * (1.f/DIMM);
    float inv = rsqrtf(var + 1e-5f);
    XN[(size_t)row*DIMM + j] = d*inv*ga[j] + ba[j];
}

// ---------------- combine split-K + bias + residual -> X, then LN -> XN ----------------
__global__ void combine_ln_kernel(const float* __restrict__ P, int ns,
                                  const float* __restrict__ bias, const float* __restrict__ R,
                                  const float* __restrict__ g, const float* __restrict__ bv,
                                  float* __restrict__ X, float* __restrict__ XN) {
    __shared__ float red[32];
    int row = blockIdx.x;
    int j = threadIdx.x;
    float v = bias[j] + R[(size_t)row*DIMM + j];
    for (int s = 0; s < ns; s++)
        v += P[(size_t)s*MROWS*DIMM + (size_t)row*DIMM + j];
    X[(size_t)row*DIMM + j] = v;
    float mean = block_reduce_sum(v, red) * (1.f/DIMM);
    float d = v - mean;
    float var = block_reduce_sum(d*d, red) * (1.f/DIMM);
    float inv = rsqrtf(var + 1e-5f);
    XN[(size_t)row*DIMM + j] = d*inv*g[j] + bv[j];
}

// ---------------- tf32 tensor-core GEMM: C = act(A@W + bias) [+R] ----------------
// 64x64 tile, 8 warps (4x2), warp computes 16x32 via m16n8k8 tf32 mma.
__device__ __forceinline__ float gelu_exact(float v) {
    return 0.5f * v * (1.f + erff(v * 0.70710678118654752f));
}

template<int ACT>
__global__ void gemm_tc(const float* __restrict__ A, const float* __restrict__ W,
                        const float* __restrict__ bias, const float* __restrict__ R,
                        float* __restrict__ C, int M, int K, int N) {
    __shared__ uint32_t As[16][68];   // [k][m] tf32
    __shared__ uint32_t Ws[16][68];   // [k][n] tf32
    int tid = threadIdx.x;
    int warp = tid >> 5, lane = tid & 31;
    int g = lane >> 2, t4 = lane & 3;
    int wm = (warp & 3) * 16, wn = (warp >> 2) * 32;
    int m0 = blockIdx.y * 64, n0 = blockIdx.x * 64;

    float acc[4][4];
    #pragma unroll
    for (int j = 0; j < 4; j++)
        #pragma unroll
        for (int r = 0; r < 4; r++) acc[j][r] = 0.f;

    int am = tid >> 2, ak = (tid & 3) << 2;
    int wk = tid >> 4, wn4 = (tid & 15) << 2;

    for (int k0 = 0; k0 < K; k0 += 16) {
        float4 av = make_float4(0.f, 0.f, 0.f, 0.f);
        if (m0 + am < M)
            av = *(const float4*)&A[(size_t)(m0 + am)*K + k0 + ak];
        As[ak + 0][am] = f2tf32(av.x); As[ak + 1][am] = f2tf32(av.y);
        As[ak + 2][am] = f2tf32(av.z); As[ak + 3][am] = f2tf32(av.w);
        #pragma unroll
        for (int e = 0; e < 4; e++) {
            int n = n0 + wn4 + e;
            Ws[wk][wn4 + e] = (n < N) ? f2tf32(W[(size_t)(k0 + wk)*N + n]) : 0u;
        }
        __syncthreads();
        #pragma unroll
        for (int t = 0; t < 2; t++) {
            int kb = t*8;
            uint32_t a[4];
            a[0] = As[kb + t4][wm + g];
            a[1] = As[kb + t4][wm + g + 8];
            a[2] = As[kb + t4 + 4][wm + g];
            a[3] = As[kb + t4 + 4][wm + g + 8];
            #pragma unroll
            for (int j = 0; j < 4; j++) {
                uint32_t b[2];
                b[0] = Ws[kb + t4][wn + j*8 + g];
                b[1] = Ws[kb + t4 + 4][wn + j*8 + g];
                mma1688_tf32(acc[j], a, b);
            }
        }
        __syncthreads();
    }

    int r0 = m0 + wm + g, r1 = r0 + 8;
    #pragma unroll
    for (int j = 0; j < 4; j++) {
        int c0 = n0 + wn + j*8 + 2*t4;
        #pragma unroll
        for (int e = 0; e < 2; e++) {
            int cc = c0 + e;
            if (cc >= N) continue;
            if (r0 < M) {
                float v = acc[j][e] + bias[cc];
                if (ACT == 1) v = gelu_exact(v);
                if (R != nullptr) v += R[(size_t)r0*N + cc];
                C[(size_t)r0*N + cc] = v;
            }
            if (r1 < M) {
                float v = acc[j][2 + e] + bias[cc];
                if (ACT == 1) v = gelu_exact(v);
                if (R != nullptr) v += R[(size_t)r1*N + cc];
                C[(size_t)r1*N + cc] = v;
            }
        }
    }
}

// split-K tf32 GEMM: partial slabs (no bias/act); A row stride = klen*gridDim.z
__global__ void gemm_tc_part(const float* __restrict__ A, const float* __restrict__ W,
                             float* __restrict__ P, int M, int N, int klen) {
    __shared__ uint32_t As[16][68];
    __shared__ uint32_t Ws[16][68];
    int tid = threadIdx.x;
    int warp = tid >> 5, lane = tid & 31;
    int g = lane >> 2, t4 = lane & 3;
    int wm = (warp & 3) * 16, wn = (warp >> 2) * 32;
    int m0 = blockIdx.y * 64, n0 = blockIdx.x * 64;
    int kstart = blockIdx.z * klen;
    int Kfull = klen * gridDim.z;
    float* C = P + (size_t)blockIdx.z * M * N;

    float acc[4][4];
    #pragma unroll
    for (int j = 0; j < 4; j++)
        #pragma unroll
        for (int r = 0; r < 4; r++) acc[j][r] = 0.f;

    int am = tid >> 2, ak = (tid & 3) << 2;
    int wk = tid >> 4, wn4 = (tid & 15) << 2;

    for (int k0 = kstart; k0 < kstart + klen; k0 += 16) {
        float4 av = make_float4(0.f, 0.f, 0.f, 0.f);
        if (m0 + am < M)
            av = *(const float4*)&A[(size_t)(m0 + am)*Kfull + k0 + ak];
        As[ak + 0][am] = f2tf32(av.x); As[ak + 1][am] = f2tf32(av.y);
        As[ak + 2][am] = f2tf32(av.z); As[ak + 3][am] = f2tf32(av.w);
        #pragma unroll
        for (int e = 0; e < 4; e++) {
            int n = n0 + wn4 + e;
            Ws[wk][wn4 + e] = (n < N) ? f2tf32(W[(size_t)(k0 + wk)*N + n]) : 0u;
        }
        __syncthreads();
        #pragma unroll
        for (int t = 0; t < 2; t++) {
            int kb = t*8;
            uint32_t a[4];
            a[0] = As[kb + t4][wm + g];
            a[1] = As[kb + t4][wm + g + 8];
            a[2] = As[kb + t4 + 4][wm + g];
            a[3] = As[kb + t4 + 4][wm + g + 8];
            #pragma unroll
            for (int j = 0; j < 4; j++) {
                uint32_t b[2];
                b[0] = Ws[kb + t4][wn + j*8 + g];
                b[1] = Ws[kb + t4 + 4][wn + j*8 + g];
                mma1688_tf32(acc[j], a, b);
            }
        }
        __syncthreads();
    }

    int r0 = m0 + wm + g, r1 = r0 + 8;
    #pragma unroll
    for (int j = 0; j < 4; j++) {
        int c0 = n0 + wn + j*8 + 2*t4;
        #pragma unroll
        for (int e = 0; e < 2; e++) {
            int cc = c0 + e;
            if (cc >= N) continue;
            if (r0 < M) C[(size_t)r0*N + cc] = acc[j][e];
            if (r1 < M) C[(size_t)r1*N + cc] = acc[j][2 + e];
        }
    }
}

// ---------------- tritt v3 tile: mma + exp (no max) + marginal atomics ----------------
template<int NJ>
__device__ __forceinline__ void tt_tile3(
    int tbase, uint32_t su, uint32_t sb, const uint32_t* cs,
    float* rowm, float* colm, int warp, int lane)
{
    const int g = lane >> 2, t4 = lane & 3;

    float acc[2][NJ][4];
    #pragma unroll
    for (int mc = 0; mc < 2; mc++)
        #pragma unroll
        for (int j = 0; j < NJ; j++)
            #pragma unroll
            for (int r = 0; r < 4; r++) acc[mc][j][r] = 0.f;

    const int arow = (lane & 7) + ((lane >> 3) & 1) * 8;
    const int akb  = (lane >> 4) << 4;
    const int l2   = lane & 15;
    const int brow = l2 & 7;
    const int bkb  = (l2 >> 3) << 4;

    #pragma unroll
    for (int ks = 0; ks < 4; ks++) {
        uint32_t a[2][4];
        #pragma unroll
        for (int mc = 0; mc < 2; mc++) {
            int row = warp*32 + mc*16 + arow;
            ldm_x4(su + swz((uint32_t)(row*128 + ks*32 + akb)), a[mc]);
            a[mc][0] = hmul2u(a[mc][0], cs[ks*2+0]);
            a[mc][1] = hmul2u(a[mc][1], cs[ks*2+0]);
            a[mc][2] = hmul2u(a[mc][2], cs[ks*2+1]);
            a[mc][3] = hmul2u(a[mc][3], cs[ks*2+1]);
        }
        uint32_t b[NJ][2];
        #pragma unroll
        for (int j = 0; j < NJ; j++) {
            int row = tbase + j*8 + brow;
            ldm_x2(sb + swz((uint32_t)(row*128 + ks*32 + bkb)), b[j]);
        }
        #pragma unroll
        for (int mc = 0; mc < 2; mc++)
            #pragma unroll
            for (int j = 0; j < NJ; j++)
                mma16816(acc[mc][j], a[mc], b[j]);
    }

    bool vr[4];
    #pragma unroll
    for (int i = 0; i < 4; i++)
        vr[i] = (warp*32 + (i >> 1)*16 + (i & 1)*8 + g) < TQ;

    float rsum[4] = {0.f, 0.f, 0.f, 0.f};
    #pragma unroll
    for (int mc = 0; mc < 2; mc++) {
        #pragma unroll
        for (int j = 0; j < NJ; j++) {
            int c0 = tbase + j*8 + 2*t4;
            bool vc0 = c0 < TQ, vc1 = (c0 + 1) < TQ;
            float e0 = (vr[mc*2]   && vc0) ? __expf(acc[mc][j][0]) : 0.f;
            float e1 = (vr[mc*2]   && vc1) ? __expf(acc[mc][j][1]) : 0.f;
            float e2 = (vr[mc*2+1] && vc0) ? __expf(acc[mc][j][2]) : 0.f;
            float e3 = (vr[mc*2+1] && vc1) ? __expf(acc[mc][j][3]) : 0.f;
            acc[mc][j][0] = e0; acc[mc][j][1] = e1;
            acc[mc][j][2] = e2; acc[mc][j][3] = e3;
            rsum[mc*2]   += e0 + e1;
            rsum[mc*2+1] += e2 + e3;
        }
    }
    #pragma unroll
    for (int i = 0; i < 4; i++) {
        rsum[i] += __shfl_xor_sync(0xffffffffu, rsum[i], 1);
        rsum[i] += __shfl_xor_sync(0xffffffffu, rsum[i], 2);
    }
    if (t4 == 0) {
        #pragma unroll
        for (int i = 0; i < 4; i++) {
            int r = warp*32 + (i >> 1)*16 + (i & 1)*8 + g;
            if (r < TQ) atomicAdd(&rowm[r], rsum[i]);
        }
    }
    #pragma unroll
    for (int j = 0; j < NJ; j++) {
        float cs0 = acc[0][j][0] + acc[0][j][2] + acc[1][j][0] + acc[1][j][2];
        float cs1 = acc[0][j][1] + acc[0][j][3] + acc[1][j][1] + acc[1][j][3];
        #pragma unroll
        for (int o = 4; o <= 16; o <<= 1) {
            cs0 += __shfl_xor_sync(0xffffffffu, cs0, o);
            cs1 += __shfl_xor_sync(0xffffffffu, cs1, o);
        }
        if (g == 0) {
            int c0 = tbase + j*8 + 2*t4;
            if (c0 < TQ && cs0 != 0.f) atomicAdd(&colm[c0], cs0);
            if (c0 + 1 < TQ && cs1 != 0.f) atomicAdd(&colm[c0 + 1], cs1);
        }
    }
}

// ---------------- trittention v3: one CTA per (b, h, q-block of 4) ----------------
__global__ __launch_bounds__(TT_THREADS, 2)
void tritt_mma_kernel(const float* __restrict__ abcde, float* __restrict__ Z) {
    extern __shared__ char smc[];
    float* redf = (float*)(smc + SMB_RED);
    float* cvec = (float*)(smc + SMB_CVEC);
    float* rowm = (float*)(smc + SMB_ROWM);
    float* colm = (float*)(smc + SMB_COLM);
    float* scr  = (float*)(smc + SMB_SCR);
    uint32_t su = smem_u32(smc + SMB_A);
    uint32_t sb = smem_u32(smc + SMB_B);

    const int tid = threadIdx.x;
    const int warp = tid >> 5, lane = tid & 31;
    const int t4 = lane & 3;

    int pair = blockIdx.x / NQCHUNK;
    int qc = blockIdx.x % NQCHUNK;
    int b = pair >> 2, h = pair & 3;
    const float* base = abcde + (size_t)b * TQ * FIVE;
    const int hoff = h * DH;
    int q0 = qc * QB;
    int nq = (TQ - q0 < QB) ? (TQ - q0) : QB;

    for (int idx = tid; idx < MPAD*32; idx += TT_THREADS) {
        int s = idx >> 5, dp = (idx & 31) << 1;
        uint32_t val = 0u;
        if (s < TQ) {
            float2 av = *(const float2*)&base[(size_t)s*FIVE + hoff + dp];
            __nv_bfloat162 pp = __floats2bfloat162_rn(av.x, av.y);
            val = *(uint32_t*)&pp;
        }
        *(uint32_t*)(smc + SMB_A + swz((uint32_t)(s*128 + dp*2))) = val;
    }
    for (int idx = tid; idx < BROWS*32; idx += TT_THREADS) {
        int t = idx >> 5, dp = (idx & 31) << 1;
        uint32_t val = 0u;
        if (t < TQ) {
            float2 bv = *(const float2*)&base[(size_t)t*FIVE + DIMM + hoff + dp];
            __nv_bfloat162 pp = __floats2bfloat162_rn(bv.x, bv.y);
            val = *(uint32_t*)&pp;
        }
        *(uint32_t*)(smc + SMB_B + swz((uint32_t)(t*128 + dp*2))) = val;
    }
    __syncthreads();

    for (int iq = 0; iq < nq; iq++) {
        int q = q0 + iq;
        if (tid < DH)
            cvec[tid] = base[(size_t)q*FIVE + 2*DIMM + hoff + tid] * (1.0f/DH);
        if (tid < BROWS) { rowm[tid] = 0.f; colm[tid] = 0.f; }
        __syncthreads();

        uint32_t cs[8];
        #pragma unroll
        for (int ks = 0; ks < 4; ks++) {
            #pragma unroll
            for (int hh = 0; hh < 2; hh++) {
                int k = ks*16 + 2*t4 + 8*hh;
                __nv_bfloat162 pp = __floats2bfloat162_rn(cvec[k], cvec[k+1]);
                cs[ks*2+hh] = *(uint32_t*)&pp;
            }
        }

        tt_tile3<8>(  0, su, sb, cs, rowm, colm, warp, lane);
        tt_tile3<8>( 64, su, sb, cs, rowm, colm, warp, lane);
        tt_tile3<8>(128, su, sb, cs, rowm, colm, warp, lane);
        tt_tile3<2>(192, su, sb, cs, rowm, colm, warp, lane);
        __syncthreads();

        float zs = 0.f;
        for (int i = tid; i < TQ; i += TT_THREADS) zs += rowm[i];
        float Ztot = block_reduce_sum(zs, redf);
        float inv = 1.f / Ztot;

        int d = tid & 63, ch = tid >> 6;
        float accz = 0.f;
        for (int s = ch; s < TQ; s += 4) {
            accz += rowm[s] * base[(size_t)s*FIVE + 3*DIMM + hoff + d];
            accz += colm[s] * base[(size_t)s*FIVE + 4*DIMM + hoff + d];
        }
        scr[tid] = accz;
        __syncthreads();
        if (ch == 0) {
            float tot = scr[d] + scr[64 + d] + scr[128 + d] + scr[192 + d];
            Z[((size_t)(b*TQ + q))*DIMM + hoff + d] = tot * inv;
        }
        __syncthreads();
    }
}

// ---------------- classifier head (in-block K split; XN already final-LN'd) ----------------
__global__ void head_kernel(const float* __restrict__ XN, const float* __restrict__ W,
                            const float* __restrict__ bias, float* __restrict__ out) {
    __shared__ float sacc[256];
    int tid = threadIdx.x;
    int c = tid & 63, kc = tid >> 6;
    int n = blockIdx.x * 64 + c;
    int b = blockIdx.y;
    const float* x = XN + (size_t)b * TQ * DIMM;
    float acc = 0.f;
    if (n < NCLS) {
        #pragma unroll 8
        for (int i = 0; i < 64; i++) {
            int k = kc*64 + i;
            acc += x[k] * W[(size_t)k*NCLS + n];
        }
    }
    sacc[tid] = acc;
    __syncthreads();
    if (kc == 0 && n < NCLS)
        out[(size_t)b*NCLS + n] = sacc[c] + sacc[64 + c] + sacc[128 + c] + sacc[192 + c] + bias[n];
}

// ---------------- host launch ----------------
extern "C" void kernel_launch(void* const* d_in, const int* in_sizes, int n_in,
                              void* d_out, int out_size) {
    const float* img         = (const float*)d_in[0];
    const float* patch_ln1_g = (const float*)d_in[1];
    const float* patch_ln1_b = (const float*)d_in[2];
    const float* patch_w     = (const float*)d_in[3];
    const float* patch_b     = (const float*)d_in[4];
    const float* patch_ln2_g = (const float*)d_in[5];
    const float* patch_ln2_b = (const float*)d_in[6];
    const float* pos_emb     = (const float*)d_in[7];
    const float* cls_token   = (const float*)d_in[8];
    const float* attn_ln_g   = (const float*)d_in[9];
    const float* attn_ln_b   = (const float*)d_in[10];
    const float* w_abcde     = (const float*)d_in[11];
    const float* b_abcde     = (const float*)d_in[12];
    const float* w_out       = (const float*)d_in[13];
    const float* b_out       = (const float*)d_in[14];
    const float* ff_ln_g     = (const float*)d_in[15];
    const float* ff_ln_b     = (const float*)d_in[16];
    const float* ff_w1       = (const float*)d_in[17];
    const float* ff_b1       = (const float*)d_in[18];
    const float* ff_w2       = (const float*)d_in[19];
    const float* ff_b2       = (const float*)d_in[20];
    const float* final_ln_g  = (const float*)d_in[21];
    const float* final_ln_b  = (const float*)d_in[22];
    const float* head_w      = (const float*)d_in[23];
    const float* head_b      = (const float*)d_in[24];
    float* out = (float*)d_out;

    float *pn, *x, *xn, *ab, *z, *hb, *pp;
    cudaGetSymbolAddress((void**)&pn, g_pn);
    cudaGetSymbolAddress((void**)&x,  g_x);
    cudaGetSymbolAddress((void**)&xn, g_xn);
    cudaGetSymbolAddress((void**)&ab, g_ab);
    cudaGetSymbolAddress((void**)&z,  g_z);
    cudaGetSymbolAddress((void**)&hb, g_h);
    cudaGetSymbolAddress((void**)&pp, g_part);

    cudaFuncSetAttribute(tritt_mma_kernel,
                         cudaFuncAttributeMaxDynamicSharedMemorySize, SMB_TOTAL);

    // patch embed: gather+LN1, split-K tf32 GEMM, fused combine+LN2+pos+attnLN0
    gather_ln_kernel<<<BATCH*NPATCH, 256>>>(img, patch_ln1_g, patch_ln1_b);
    gemm_tc_part<<<dim3(4, 7, 3), 256>>>(pn, patch_w, pp, BATCH*NPATCH, DIMM, 256);
    assemble_fused_kernel<<<MROWS, 256>>>(pp, patch_b, patch_ln2_g, patch_ln2_b,
                                          cls_token, pos_emb, attn_ln_g, attn_ln_b, x, xn);

    for (int L = 0; L < 2; L++) {
        gemm_tc<0><<<dim3(20, 7), 256>>>(xn, w_abcde + (size_t)L*DIMM*FIVE,
                                         b_abcde + L*FIVE, nullptr, ab,
                                         MROWS, DIMM, FIVE);
        tritt_mma_kernel<<<BATCH*HEADS*NQCHUNK, TT_THREADS, SMB_TOTAL>>>(ab, z);
        gemm_tc<0><<<dim3(4, 7), 256>>>(z, w_out + (size_t)L*DIMM*DIMM,
                                        b_out + L*DIMM, x, x,
                                        MROWS, DIMM, DIMM);
        ln_kernel<<<MROWS, 256>>>(x, ff_ln_g + L*DIMM, ff_ln_b + L*DIMM, xn);
        gemm_tc<1><<<dim3(16, 7), 256>>>(xn, ff_w1 + (size_t)L*DIMM*MLPD,
                                         ff_b1 + L*MLPD, nullptr, hb,
                                         MROWS, DIMM, MLPD);
        gemm_tc_part<<<dim3(4, 7, 4), 256>>>(hb, ff_w2 + (size_t)L*MLPD*DIMM,
                                             pp, MROWS, DIMM, 256);
        const float* ng = (L == 0) ? (attn_ln_g + DIMM) : final_ln_g;
        const float* nb = (L == 0) ? (attn_ln_b + DIMM) : final_ln_b;
        combine_ln_kernel<<<MROWS, 256>>>(pp, 4, ff_b2 + L*DIMM, x, ng, nb, x, xn);
    }

    head_kernel<<<dim3(16, BATCH), 256>>>(xn, head_w, head_b, out);
}